// round 14
// baseline (speedup 1.0000x reference)
#include <cuda_runtime.h>
#include <cuda_bf16.h>
#include <cuda_fp16.h>
#include <math.h>
#include <stdint.h>

#define DM   1024
#define NSEQ 2048
#define NB   2
#define NH   16
#define HD   64
#define MROWS (NB*NSEQ)          // 4096
#define NELEM ((size_t)MROWS*DM) // 4,194,304
#define WELEM ((size_t)DM*DM)    // 1,048,576

// ---------------- scratch (__device__ globals; no allocations) -------------
__device__ __half gW[4*WELEM];                // weights single fp16
__device__ __half gQ[NELEM];                  // (b,h,n,d), Q pre-scaled
__device__ __half gK[NELEM];                  // K single fp16
__device__ __half gV[NELEM];                  // V single fp16
__device__ __half gO[NELEM];                  // attn out (b*n, h*d), single

// ---------------- PTX helpers ---------------------------------------------
__device__ __forceinline__ void mma16816h(float* c,
    unsigned a0, unsigned a1, unsigned a2, unsigned a3,
    unsigned b0, unsigned b1)
{
    asm volatile(
        "mma.sync.aligned.m16n8k16.row.col.f32.f16.f16.f32 "
        "{%0,%1,%2,%3},{%4,%5,%6,%7},{%8,%9},{%0,%1,%2,%3};"
        : "+f"(c[0]), "+f"(c[1]), "+f"(c[2]), "+f"(c[3])
        : "r"(a0), "r"(a1), "r"(a2), "r"(a3), "r"(b0), "r"(b1));
}

__device__ __forceinline__ void ldm_x4(unsigned& r0, unsigned& r1,
                                       unsigned& r2, unsigned& r3,
                                       const void* p)
{
    unsigned a = (unsigned)__cvta_generic_to_shared(p);
    asm volatile("ldmatrix.sync.aligned.m8n8.x4.shared.b16 {%0,%1,%2,%3},[%4];"
                 : "=r"(r0), "=r"(r1), "=r"(r2), "=r"(r3) : "r"(a));
}

__device__ __forceinline__ void ldm_x2(unsigned& r0, unsigned& r1, const void* p)
{
    unsigned a = (unsigned)__cvta_generic_to_shared(p);
    asm volatile("ldmatrix.sync.aligned.m8n8.x2.shared.b16 {%0,%1},[%2];"
                 : "=r"(r0), "=r"(r1) : "r"(a));
}

__device__ __forceinline__ void ldm_x2t(unsigned& r0, unsigned& r1, const void* p)
{
    unsigned a = (unsigned)__cvta_generic_to_shared(p);
    asm volatile("ldmatrix.sync.aligned.m8n8.x2.trans.shared.b16 {%0,%1},[%2];"
                 : "=r"(r0), "=r"(r1) : "r"(a));
}

__device__ __forceinline__ void cp16(void* dst, const void* src)
{
    unsigned d = (unsigned)__cvta_generic_to_shared(dst);
    asm volatile("cp.async.cg.shared.global [%0], [%1], 16;" :: "r"(d), "l"(src));
}
#define CP_COMMIT() asm volatile("cp.async.commit_group;")
#define CP_WAIT0()  asm volatile("cp.async.wait_group 0;")

__device__ __forceinline__ void sts128(void* dst, unsigned r0, unsigned r1,
                                       unsigned r2, unsigned r3)
{
    unsigned d = (unsigned)__cvta_generic_to_shared(dst);
    asm volatile("st.shared.v4.b32 [%0], {%1,%2,%3,%4};"
                 :: "r"(d), "r"(r0), "r"(r1), "r"(r2), "r"(r3));
}

__device__ __forceinline__ unsigned pack_h2(float x, float y)
{
    __half2 p = __floats2half2_rn(x, y);
    return *(unsigned*)&p;
}

// 16B-chunk XOR swizzle for 64-col fp16 tiles (row*64 elems + chunk^row&7)
__device__ __forceinline__ int swz64(int r, int c8)
{
    return r * 64 + ((c8 ^ (r & 7)) * 8);
}

// ---------------- weights fp32 -> fp16 conversion --------------------------
#define NF4_W  (WELEM >> 2)   // 2^18 float4 per weight tensor

__global__ void split_all(const float* __restrict__ wq, const float* __restrict__ wk,
                          const float* __restrict__ wv, const float* __restrict__ wo)
{
    for (size_t i = blockIdx.x * blockDim.x + threadIdx.x; i < 4*NF4_W;
         i += (size_t)gridDim.x * blockDim.x) {
        int slot = (int)(i >> 18);
        size_t off = i & (NF4_W - 1);
        const float* src = (slot == 0) ? wq : (slot == 1) ? wk
                         : (slot == 2) ? wv : wo;
        __half* h = gW + (size_t)slot * WELEM;
        float4 val = ((const float4*)src)[off];
        ((uint2*)h)[off] = make_uint2(pack_h2(val.x, val.y),
                                      pack_h2(val.z, val.w));
    }
}

// ---------------- GEMM: BK=64, swizzled 64-col tiles, dynamic smem ---------
#define GTILE   (128*64)                 // elems per tile
#define GSMEM   (4*GTILE*2)              // bytes = 65536 (2 stages x 2 tiles)

// one k-step (16 wide) = 16 MMAs; kk in 0..3
#define GEMM_KSTEP64(kk)                                                      \
    {                                                                         \
        unsigned bf[4][2];                                                    \
        _Pragma("unroll")                                                     \
        for (int ni = 0; ni < 4; ni++) {                                      \
            int off = swz64(wn + ni * 8 + br, (kk) * 2 + bchk);               \
            ldm_x2(bf[ni][0], bf[ni][1], &sB[st * GTILE + off]);              \
        }                                                                     \
        _Pragma("unroll")                                                     \
        for (int mp = 0; mp < 2; mp++) {                                      \
            unsigned ah[2][4];                                                \
            _Pragma("unroll")                                                 \
            for (int q = 0; q < 2; q++) {                                     \
                int off = swz64(wm + (mp * 2 + q) * 16 + ar, (kk) * 2 + achk);\
                ldm_x4(ah[q][0], ah[q][1], ah[q][2], ah[q][3],                \
                       &sA[st * GTILE + off]);                                \
            }                                                                 \
            _Pragma("unroll")                                                 \
            for (int q = 0; q < 2; q++)                                       \
                _Pragma("unroll")                                             \
                for (int ni = 0; ni < 4; ni++)                                \
                    mma16816h(c[mp * 2 + q][ni], ah[q][0], ah[q][1],          \
                              ah[q][2], ah[q][3], bf[ni][0], bf[ni][1]);      \
        }                                                                     \
    }

// B-only stage load (fp16 weights via cp.async): 1024 chunks, 4/thread
#define GEMM_LOAD_B64(dstB, koff)                                             \
    {                                                                         \
        _Pragma("unroll")                                                     \
        for (int u = 0; u < 4; u++) {                                         \
            int id = tid + u * 256;                                           \
            int r = id >> 3, c8 = id & 7;                                     \
            cp16(&(dstB)[swz64(r, c8)], gB + (size_t)r * DM + (koff) + c8*8); \
        }                                                                     \
    }

// A+B stage load (both fp16 via cp.async) — used by gemm_out
#define GEMM_LOAD_STAGE64(dstA, dstB, koff)                                   \
    {                                                                         \
        _Pragma("unroll")                                                     \
        for (int u = 0; u < 4; u++) {                                         \
            int id = tid + u * 256;                                           \
            int r = id >> 3, c8 = id & 7;                                     \
            int sw = swz64(r, c8);                                            \
            cp16(&(dstA)[sw], gA + (size_t)r * DM + (koff) + c8 * 8);         \
            cp16(&(dstB)[sw], gB + (size_t)r * DM + (koff) + c8 * 8);         \
        }                                                                     \
    }

// A-side fp32 load batch (2 chunks: u = ub*2, ub*2+1)
#define A32_LDG(ub, koff)                                                     \
    {                                                                         \
        _Pragma("unroll")                                                     \
        for (int u = 0; u < 2; u++) {                                         \
            int id = tid + ((ub) * 2 + u) * 256;                              \
            int r = id >> 3, c8 = id & 7;                                     \
            const float* p = gA32 + (size_t)r * DM + (koff) + c8 * 8;         \
            af[u][0] = *(const float4*)p;                                     \
            af[u][1] = *(const float4*)(p + 4);                               \
        }                                                                     \
    }

// convert + store batch into dst stage
#define A32_STS(ub, dstA)                                                     \
    {                                                                         \
        _Pragma("unroll")                                                     \
        for (int u = 0; u < 2; u++) {                                         \
            int id = tid + ((ub) * 2 + u) * 256;                              \
            int r = id >> 3, c8 = id & 7;                                     \
            sts128(&(dstA)[swz64(r, c8)],                                     \
                   pack_h2(af[u][0].x, af[u][0].y),                           \
                   pack_h2(af[u][0].z, af[u][0].w),                           \
                   pack_h2(af[u][1].x, af[u][1].y),                           \
                   pack_h2(af[u][1].z, af[u][1].w));                          \
        }                                                                     \
    }

// ---------------- QKV projection GEMM (fused fp32->fp16 A-side) ------------
__global__ __launch_bounds__(256, 2) void gemm_qkv(
    const float* __restrict__ Xq, const float* __restrict__ Xk,
    const float* __restrict__ Xv,
    const float* __restrict__ bq, const float* __restrict__ bk,
    const float* __restrict__ bv)
{
    extern __shared__ __half gsm[];
    __half* sA = gsm;                // [2][GTILE]
    __half* sB = gsm + 2 * GTILE;    // [2][GTILE]

    const int z = blockIdx.z;
    const float* Xp = (z == 0) ? Xq : (z == 1) ? Xk : Xv;
    const __half* Wp = gW + (size_t)z * WELEM;
    const float* bias = (z == 0) ? bq : (z == 1) ? bk : bv;
    const float scale = (z == 0) ? 0.125f : 1.0f;

    const int tid = threadIdx.x, lane = tid & 31, warp = tid >> 5;
    const int m0 = blockIdx.y * 128, n0 = blockIdx.x * 128;
    const int wm = (warp & 1) * 64, wn = (warp >> 1) * 32;

    const float* gA32 = Xp + (size_t)m0 * DM;
    const __half* gB  = Wp + (size_t)n0 * DM;

    float c[4][4][4];
    #pragma unroll
    for (int i = 0; i < 4; i++)
        #pragma unroll
        for (int j = 0; j < 4; j++)
            #pragma unroll
            for (int r = 0; r < 4; r++) c[i][j][r] = 0.0f;

    // prologue: A stage0 (fp32 load + convert + STS), B stage0 (cp.async)
    {
        float4 af[2][2];
        A32_LDG(0, 0) A32_STS(0, sA)
        A32_LDG(1, 0) A32_STS(1, sA)
    }
    GEMM_LOAD_B64(sB, 0)
    CP_COMMIT();

    const int ar = lane & 15, achk = lane >> 4;
    const int br = lane & 7,  bchk = (lane >> 3) & 1;

    for (int kt = 0; kt < 16; kt++) {
        const int st = kt & 1;
        CP_WAIT0();
        __syncthreads();
        const bool pf = (kt < 15);
        __half* nA = sA + (st ^ 1) * GTILE;
        const int nko = (kt + 1) * 64;

        float4 af[2][2];
        if (pf) {
            A32_LDG(0, nko)
            GEMM_LOAD_B64(sB + (st ^ 1) * GTILE, nko)
            CP_COMMIT();
        }
        GEMM_KSTEP64(0)
        GEMM_KSTEP64(1)
        if (pf) {
            A32_STS(0, nA)
            A32_LDG(1, nko)
        }
        GEMM_KSTEP64(2)
        GEMM_KSTEP64(3)
        if (pf) {
            A32_STS(1, nA)
        }
    }

    // epilogue: + bias, * scale(Q), convert, scatter to (b,h,n,d)
    const int r0 = lane >> 2, cq = (lane & 3) * 2;
    #pragma unroll
    for (int mi = 0; mi < 4; mi++) {
        #pragma unroll
        for (int ni = 0; ni < 4; ni++) {
            int col = n0 + wn + ni * 8 + cq;
            float b0 = bias[col], b1 = bias[col + 1];
            int hh = col >> 6, d = col & 63;
            #pragma unroll
            for (int half = 0; half < 2; half++) {
                int row = m0 + wm + mi * 16 + r0 + half * 8;
                float v0 = (c[mi][ni][half * 2 + 0] + b0) * scale;
                float v1 = (c[mi][ni][half * 2 + 1] + b1) * scale;
                int bb = row >> 11, n = row & (NSEQ - 1);
                size_t idx = (((size_t)(bb * NH + hh)) * NSEQ + n) * HD + d;
                unsigned pv = pack_h2(v0, v1);
                if (z == 0)      *(unsigned*)&gQ[idx] = pv;
                else if (z == 1) *(unsigned*)&gK[idx] = pv;
                else             *(unsigned*)&gV[idx] = pv;
            }
        }
    }
}

// ---------------- output projection GEMM (1-term fp16, BK=64) --------------
__global__ __launch_bounds__(256, 2) void gemm_out(
    const float* __restrict__ bo, float* __restrict__ out)
{
    extern __shared__ __half gsm[];
    __half* sA = gsm;
    __half* sB = gsm + 2 * GTILE;

    const __half* Wp = gW + 3 * WELEM;

    const int tid = threadIdx.x, lane = tid & 31, warp = tid >> 5;
    const int m0 = blockIdx.y * 128, n0 = blockIdx.x * 128;
    const int wm = (warp & 1) * 64, wn = (warp >> 1) * 32;

    const __half* gA = gO + (size_t)m0 * DM;
    const __half* gB = Wp + (size_t)n0 * DM;

    float c[4][4][4];
    #pragma unroll
    for (int i = 0; i < 4; i++)
        #pragma unroll
        for (int j = 0; j < 4; j++)
            #pragma unroll
            for (int r = 0; r < 4; r++) c[i][j][r] = 0.0f;

    GEMM_LOAD_STAGE64(sA, sB, 0)
    CP_COMMIT();

    const int ar = lane & 15, achk = lane >> 4;
    const int br = lane & 7,  bchk = (lane >> 3) & 1;

    for (int kt = 0; kt < 16; kt++) {
        const int st = kt & 1;
        CP_WAIT0();
        __syncthreads();
        if (kt < 15) {
            GEMM_LOAD_STAGE64(sA + (st ^ 1) * GTILE, sB + (st ^ 1) * GTILE,
                              (kt + 1) * 64)
            CP_COMMIT();
        }
        GEMM_KSTEP64(0)
        GEMM_KSTEP64(1)
        GEMM_KSTEP64(2)
        GEMM_KSTEP64(3)
    }

    const int r0 = lane >> 2, cq = (lane & 3) * 2;
    #pragma unroll
    for (int mi = 0; mi < 4; mi++) {
        #pragma unroll
        for (int ni = 0; ni < 4; ni++) {
            int col = n0 + wn + ni * 8 + cq;
            float b0 = bo[col], b1 = bo[col + 1];
            #pragma unroll
            for (int half = 0; half < 2; half++) {
                int row = m0 + wm + mi * 16 + r0 + half * 8;
                float2 v = make_float2(c[mi][ni][half * 2 + 0] + b0,
                                       c[mi][ni][half * 2 + 1] + b1);
                *(float2*)&out[(size_t)row * DM + col] = v;
            }
        }
    }
}

// ---------------- flash attention -------------------------------------------
// S: Q fp16 x K fp16 (1 MMA). PV: P fp16 x V fp16 (1 MMA).
// XOR-swizzled smem: Q 128x64, KV 2 stages x 2 x 64x64. 49,152 B -> 2 CTAs/SM.
#define QTSZ   (128*64)              // elems per Q tile
#define KVTSZ  (64*64)               // elems per K/V tile
#define KVSTG  (2*KVTSZ)             // elems per KV stage [K, V]
#define FLASH_SMEM ((QTSZ + 2*KVSTG) * 2)   // bytes = 49152

__global__ __launch_bounds__(256, 2) void flash()
{
    extern __shared__ __half sm[];
    __half* sQ  = sm;                 // [128x64] swizzled
    __half* sKV = sm + QTSZ;          // [stage][K,V][64x64]

    const int tid = threadIdx.x, lane = tid & 31, warp = tid >> 5;
    const int bh = blockIdx.y, q0 = blockIdx.x * 128;
    const size_t base = (size_t)bh * NSEQ * HD;

    // Q tile: 1024 chunks; 4 per thread
    #pragma unroll
    for (int u = 0; u < 4; u++) {
        int id = tid + u * 256;
        int r = id >> 3, c8 = id & 7;
        cp16(&sQ[swz64(r, c8)], gQ + base + (size_t)(q0 + r) * HD + c8 * 8);
    }
    // KV stage 0: 2 x 512 chunks; 4 per thread
    #pragma unroll
    for (int u = 0; u < 4; u++) {
        int id = tid + u * 256;
        int t = id >> 9, rem = id & 511;
        int r = rem >> 3, c8 = rem & 7;
        size_t g = base + (size_t)r * HD + c8 * 8;
        const void* src = (t == 0) ? (const void*)(gK + g)
                                   : (const void*)(gV + g);
        cp16(&sKV[t * KVTSZ + swz64(r, c8)], src);
    }
    CP_COMMIT();

    float o[8][4];
    #pragma unroll
    for (int i = 0; i < 8; i++)
        #pragma unroll
        for (int j = 0; j < 4; j++) o[i][j] = 0.0f;
    float mr0 = -1e30f, mr1 = -1e30f, lr0 = 0.0f, lr1 = 0.0f;

    const int ar = lane & 15;
    const int achk = lane >> 4;          // A-operand chunk half
    const int br = lane & 7;
    const int bchk = (lane >> 3) & 1;    // B-operand chunk half

    for (int kt = 0; kt < NSEQ / 64; kt++) {
        const int st = kt & 1;
        CP_WAIT0();
        __syncthreads();
        if (kt < NSEQ / 64 - 1) {
            __half* d = sKV + (st ^ 1) * KVSTG;
            size_t kb = base + (size_t)(kt + 1) * 64 * HD;
            #pragma unroll
            for (int u = 0; u < 4; u++) {
                int id = tid + u * 256;
                int t = id >> 9, rem = id & 511;
                int r = rem >> 3, c8 = rem & 7;
                size_t g = kb + (size_t)r * HD + c8 * 8;
                const void* src = (t == 0) ? (const void*)(gK + g)
                                           : (const void*)(gV + g);
                cp16(&d[t * KVTSZ + swz64(r, c8)], src);
            }
            CP_COMMIT();
        }

        const __half* Ks = sKV + st * KVSTG;
        const __half* Vs = Ks + KVTSZ;

        float s[8][4];
        #pragma unroll
        for (int i = 0; i < 8; i++)
            #pragma unroll
            for (int j = 0; j < 4; j++) s[i][j] = 0.0f;

        // S = Q.K^T — 1 term, term-major over ni-quads
        #pragma unroll
        for (int kk = 0; kk < 4; kk++) {
            unsigned ah[4];
            int arow = warp * 16 + ar;
            int aoff = swz64(arow, kk * 2 + achk);
            ldm_x4(ah[0], ah[1], ah[2], ah[3], &sQ[aoff]);
            #pragma unroll
            for (int nh = 0; nh < 2; nh++) {
                unsigned kb4[4][2];
                #pragma unroll
                for (int nq = 0; nq < 4; nq++) {
                    int krow = (nh * 4 + nq) * 8 + br;
                    int koff = swz64(krow, kk * 2 + bchk);
                    ldm_x2(kb4[nq][0], kb4[nq][1], &Ks[koff]);
                }
                #pragma unroll
                for (int nq = 0; nq < 4; nq++)
                    mma16816h(s[nh * 4 + nq], ah[0], ah[1], ah[2], ah[3],
                              kb4[nq][0], kb4[nq][1]);
            }
        }

        float mx0 = -1e30f, mx1 = -1e30f;
        #pragma unroll
        for (int ni = 0; ni < 8; ni++) {
            mx0 = fmaxf(mx0, fmaxf(s[ni][0], s[ni][1]));
            mx1 = fmaxf(mx1, fmaxf(s[ni][2], s[ni][3]));
        }
        mx0 = fmaxf(mx0, __shfl_xor_sync(0xffffffffu, mx0, 1));
        mx0 = fmaxf(mx0, __shfl_xor_sync(0xffffffffu, mx0, 2));
        mx1 = fmaxf(mx1, __shfl_xor_sync(0xffffffffu, mx1, 1));
        mx1 = fmaxf(mx1, __shfl_xor_sync(0xffffffffu, mx1, 2));

        float nm0 = fmaxf(mr0, mx0), nm1 = fmaxf(mr1, mx1);
        float cr0 = __expf(mr0 - nm0), cr1 = __expf(mr1 - nm1);
        mr0 = nm0; mr1 = nm1;

        float sum0 = 0.0f, sum1 = 0.0f;
        #pragma unroll
        for (int ni = 0; ni < 8; ni++) {
            s[ni][0] = __expf(s[ni][0] - nm0);
            s[ni][1] = __expf(s[ni][1] - nm0);
            s[ni][2] = __expf(s[ni][2] - nm1);
            s[ni][3] = __expf(s[ni][3] - nm1);
            sum0 += s[ni][0] + s[ni][1];
            sum1 += s[ni][2] + s[ni][3];
        }
        sum0 += __shfl_xor_sync(0xffffffffu, sum0, 1);
        sum0 += __shfl_xor_sync(0xffffffffu, sum0, 2);
        sum1 += __shfl_xor_sync(0xffffffffu, sum1, 1);
        sum1 += __shfl_xor_sync(0xffffffffu, sum1, 2);
        lr0 = lr0 * cr0 + sum0;
        lr1 = lr1 * cr1 + sum1;
        #pragma unroll
        for (int dj = 0; dj < 8; dj++) {
            o[dj][0] *= cr0; o[dj][1] *= cr0;
            o[dj][2] *= cr1; o[dj][3] *= cr1;
        }

        // O += P(fp16) . V(fp16) — term-major over dj-quads
        #pragma unroll
        for (int kk = 0; kk < 4; kk++) {
            unsigned p0 = pack_h2(s[2*kk][0],   s[2*kk][1]);
            unsigned p1 = pack_h2(s[2*kk][2],   s[2*kk][3]);
            unsigned p2 = pack_h2(s[2*kk+1][0], s[2*kk+1][1]);
            unsigned p3 = pack_h2(s[2*kk+1][2], s[2*kk+1][3]);
            int vrow = kk * 16 + ar;
            #pragma unroll
            for (int dh = 0; dh < 2; dh++) {
                unsigned vb4[4][2];
                #pragma unroll
                for (int dq = 0; dq < 4; dq++) {
                    int voff = swz64(vrow, dh * 4 + dq);
                    ldm_x2t(vb4[dq][0], vb4[dq][1], &Vs[voff]);
                }
                #pragma unroll
                for (int dq = 0; dq < 4; dq++)
                    mma16816h(o[dh * 4 + dq], p0, p1, p2, p3,
                              vb4[dq][0], vb4[dq][1]);
            }
        }
    }

    const int b = bh >> 4, h = bh & 15;
    const int row0 = q0 + warp * 16 + (lane >> 2);
    const float inv0 = 1.0f / lr0, inv1 = 1.0f / lr1;
    const size_t rb = ((size_t)(b * NSEQ) + row0) * DM + h * HD;
    #pragma unroll
    for (int dj = 0; dj < 8; dj++) {
        int d = dj * 8 + (lane & 3) * 2;
        *(unsigned*)&gO[rb + d] = pack_h2(o[dj][0] * inv0, o[dj][1] * inv0);
        *(unsigned*)&gO[rb + (size_t)8 * DM + d] =
            pack_h2(o[dj][2] * inv1, o[dj][3] * inv1);
    }
}

// ---------------------------------------------------------------------------
extern "C" void kernel_launch(void* const* d_in, const int* in_sizes, int n_in,
                              void* d_out, int out_size)
{
    (void)in_sizes; (void)n_in; (void)out_size;
    const float* queries = (const float*)d_in[0];
    const float* keys    = (const float*)d_in[1];
    const float* values  = (const float*)d_in[2];
    const float* Wq = (const float*)d_in[3];
    const float* bq = (const float*)d_in[4];
    const float* Wk = (const float*)d_in[5];
    const float* bk = (const float*)d_in[6];
    const float* Wv = (const float*)d_in[7];
    const float* bv = (const float*)d_in[8];
    const float* Wo = (const float*)d_in[9];
    const float* bo = (const float*)d_in[10];
    float* out = (float*)d_out;

    cudaFuncSetAttribute(flash, cudaFuncAttributeMaxDynamicSharedMemorySize,
                         FLASH_SMEM);
    cudaFuncSetAttribute(gemm_qkv, cudaFuncAttributeMaxDynamicSharedMemorySize,
                         GSMEM);
    cudaFuncSetAttribute(gemm_out, cudaFuncAttributeMaxDynamicSharedMemorySize,
                         GSMEM);

    // weights fp32 -> fp16
    split_all<<<1024, 256>>>(Wq, Wk, Wv, Wo);

    // QKV projections (input conversion fused)
    gemm_qkv<<<dim3(DM / 128, MROWS / 128, 3), 256, GSMEM>>>(
        queries, keys, values, bq, bk, bv);

    // attention
    flash<<<dim3(NSEQ / 128, NB * NH), 256, FLASH_SMEM>>>();

    // output projection
    gemm_out<<<dim3(DM / 128, MROWS / 128), 256, GSMEM>>>(bo, out);
}

// round 15
// speedup vs baseline: 1.0495x; 1.0495x over previous
#include <cuda_runtime.h>
#include <cuda_bf16.h>
#include <cuda_fp16.h>
#include <math.h>
#include <stdint.h>

#define DM   1024
#define NSEQ 2048
#define NB   2
#define NH   16
#define HD   64
#define MROWS (NB*NSEQ)          // 4096
#define NELEM ((size_t)MROWS*DM) // 4,194,304
#define WELEM ((size_t)DM*DM)    // 1,048,576

// ---------------- scratch (__device__ globals; no allocations) -------------
__device__ __half gX[3*NELEM];                // inputs q,k,v single fp16
__device__ __half gW[4*WELEM];                // weights single fp16
__device__ __half gQ[NELEM];                  // (b,h,n,d), Q pre-scaled by 0.125*log2e
__device__ __half gK[NELEM];                  // K single fp16
__device__ __half gV[NELEM];                  // V single fp16
__device__ __half gO[NELEM];                  // attn out (b*n, h*d), single

// ---------------- PTX helpers ---------------------------------------------
__device__ __forceinline__ void mma16816h(float* c,
    unsigned a0, unsigned a1, unsigned a2, unsigned a3,
    unsigned b0, unsigned b1)
{
    asm volatile(
        "mma.sync.aligned.m16n8k16.row.col.f32.f16.f16.f32 "
        "{%0,%1,%2,%3},{%4,%5,%6,%7},{%8,%9},{%0,%1,%2,%3};"
        : "+f"(c[0]), "+f"(c[1]), "+f"(c[2]), "+f"(c[3])
        : "r"(a0), "r"(a1), "r"(a2), "r"(a3), "r"(b0), "r"(b1));
}

__device__ __forceinline__ void ldm_x4(unsigned& r0, unsigned& r1,
                                       unsigned& r2, unsigned& r3,
                                       const void* p)
{
    unsigned a = (unsigned)__cvta_generic_to_shared(p);
    asm volatile("ldmatrix.sync.aligned.m8n8.x4.shared.b16 {%0,%1,%2,%3},[%4];"
                 : "=r"(r0), "=r"(r1), "=r"(r2), "=r"(r3) : "r"(a));
}

__device__ __forceinline__ void ldm_x2(unsigned& r0, unsigned& r1, const void* p)
{
    unsigned a = (unsigned)__cvta_generic_to_shared(p);
    asm volatile("ldmatrix.sync.aligned.m8n8.x2.shared.b16 {%0,%1},[%2];"
                 : "=r"(r0), "=r"(r1) : "r"(a));
}

__device__ __forceinline__ void ldm_x2t(unsigned& r0, unsigned& r1, const void* p)
{
    unsigned a = (unsigned)__cvta_generic_to_shared(p);
    asm volatile("ldmatrix.sync.aligned.m8n8.x2.trans.shared.b16 {%0,%1},[%2];"
                 : "=r"(r0), "=r"(r1) : "r"(a));
}

__device__ __forceinline__ void cp16(void* dst, const void* src)
{
    unsigned d = (unsigned)__cvta_generic_to_shared(dst);
    asm volatile("cp.async.cg.shared.global [%0], [%1], 16;" :: "r"(d), "l"(src));
}
#define CP_COMMIT() asm volatile("cp.async.commit_group;")
#define CP_WAIT0()  asm volatile("cp.async.wait_group 0;")

__device__ __forceinline__ unsigned pack_h2(float x, float y)
{
    __half2 p = __floats2half2_rn(x, y);
    return *(unsigned*)&p;
}

__device__ __forceinline__ float ex2a(float x)
{
    float r;
    asm("ex2.approx.f32 %0, %1;" : "=f"(r) : "f"(x));
    return r;
}

// 16B-chunk XOR swizzle for 64-col fp16 tiles (row*64 elems + chunk^row&7)
__device__ __forceinline__ int swz64(int r, int c8)
{
    return r * 64 + ((c8 ^ (r & 7)) * 8);
}

// ---------------- merged fp32 -> fp16 conversion (single launch) -----------
#define NF4_IN (NELEM >> 2)   // 2^20 float4 per input tensor
#define NF4_W  (WELEM >> 2)   // 2^18 float4 per weight tensor
#define NF4_TOT (3*NF4_IN + 4*NF4_W)

__global__ void split_all(const float* __restrict__ q, const float* __restrict__ k,
                          const float* __restrict__ v, const float* __restrict__ wq,
                          const float* __restrict__ wk, const float* __restrict__ wv,
                          const float* __restrict__ wo)
{
    for (size_t i = blockIdx.x * blockDim.x + threadIdx.x; i < NF4_TOT;
         i += (size_t)gridDim.x * blockDim.x) {
        const float* src;
        __half* h;
        size_t off;
        if (i < 3*NF4_IN) {
            int slot = (int)(i >> 20);
            off = i & (NF4_IN - 1);
            src = (slot == 0) ? q : (slot == 1) ? k : v;
            h = gX + (size_t)slot * NELEM;
        } else {
            size_t j = i - 3*NF4_IN;
            int slot = (int)(j >> 18);
            off = j & (NF4_W - 1);
            src = (slot == 0) ? wq : (slot == 1) ? wk : (slot == 2) ? wv : wo;
            h = gW + (size_t)slot * WELEM;
        }
        float4 val = ((const float4*)src)[off];
        ((uint2*)h)[off] = make_uint2(pack_h2(val.x, val.y),
                                      pack_h2(val.z, val.w));
    }
}

// ---------------- GEMM: BK=64, swizzled 64-col tiles, dynamic smem ---------
#define GTILE   (128*64)                 // elems per tile
#define GSMEM   (4*GTILE*2)              // bytes = 65536 (2 stages x 2 tiles)

// stage load: A,B tiles 128 rows x 8 chunks; 2048 chunks total, 8 per thread
#define GEMM_LOAD_STAGE64(dstA, dstB, koff)                                   \
    {                                                                         \
        _Pragma("unroll")                                                     \
        for (int u = 0; u < 4; u++) {                                         \
            int id = tid + u * 256;                                           \
            int r = id >> 3, c8 = id & 7;                                     \
            int sw = swz64(r, c8);                                            \
            cp16(&(dstA)[sw], gA + (size_t)r * DM + (koff) + c8 * 8);         \
            cp16(&(dstB)[sw], gB + (size_t)r * DM + (koff) + c8 * 8);         \
        }                                                                     \
    }

// one k-step (16 wide) = 16 MMAs; kk in 0..3
#define GEMM_KSTEP64(kk)                                                      \
    {                                                                         \
        unsigned bf[4][2];                                                    \
        _Pragma("unroll")                                                     \
        for (int ni = 0; ni < 4; ni++) {                                      \
            int off = swz64(wn + ni * 8 + br, (kk) * 2 + bchk);               \
            ldm_x2(bf[ni][0], bf[ni][1], &sB[st * GTILE + off]);              \
        }                                                                     \
        _Pragma("unroll")                                                     \
        for (int mp = 0; mp < 2; mp++) {                                      \
            unsigned ah[2][4];                                                \
            _Pragma("unroll")                                                 \
            for (int q = 0; q < 2; q++) {                                     \
                int off = swz64(wm + (mp * 2 + q) * 16 + ar, (kk) * 2 + achk);\
                ldm_x4(ah[q][0], ah[q][1], ah[q][2], ah[q][3],                \
                       &sA[st * GTILE + off]);                                \
            }                                                                 \
            _Pragma("unroll")                                                 \
            for (int q = 0; q < 2; q++)                                       \
                _Pragma("unroll")                                             \
                for (int ni = 0; ni < 4; ni++)                                \
                    mma16816h(c[mp * 2 + q][ni], ah[q][0], ah[q][1],          \
                              ah[q][2], ah[q][3], bf[ni][0], bf[ni][1]);      \
        }                                                                     \
    }

// ---------------- QKV projection GEMM (1-term fp16, BK=64) -----------------
__global__ __launch_bounds__(256, 2) void gemm_qkv(
    const float* __restrict__ bq, const float* __restrict__ bk,
    const float* __restrict__ bv)
{
    extern __shared__ __half gsm[];
    __half* sA = gsm;                // [2][GTILE]
    __half* sB = gsm + 2 * GTILE;    // [2][GTILE]

    const int z = blockIdx.z;
    const __half* Xp = gX + (size_t)z * NELEM;
    const __half* Wp = gW + (size_t)z * WELEM;
    const float* bias = (z == 0) ? bq : (z == 1) ? bk : bv;
    // Q scale folds softmax 1/sqrt(64) AND log2(e) for the ex2-domain softmax
    const float scale = (z == 0) ? 0.125f * 1.44269504f : 1.0f;

    const int tid = threadIdx.x, lane = tid & 31, warp = tid >> 5;
    const int m0 = blockIdx.y * 128, n0 = blockIdx.x * 128;
    const int wm = (warp & 1) * 64, wn = (warp >> 1) * 32;

    const __half* gA = Xp + (size_t)m0 * DM;
    const __half* gB = Wp + (size_t)n0 * DM;

    float c[4][4][4];
    #pragma unroll
    for (int i = 0; i < 4; i++)
        #pragma unroll
        for (int j = 0; j < 4; j++)
            #pragma unroll
            for (int r = 0; r < 4; r++) c[i][j][r] = 0.0f;

    GEMM_LOAD_STAGE64(sA, sB, 0)
    CP_COMMIT();

    const int ar = lane & 15, achk = lane >> 4;
    const int br = lane & 7,  bchk = (lane >> 3) & 1;

    for (int kt = 0; kt < 16; kt++) {
        const int st = kt & 1;
        CP_WAIT0();
        __syncthreads();
        if (kt < 15) {
            GEMM_LOAD_STAGE64(sA + (st ^ 1) * GTILE, sB + (st ^ 1) * GTILE,
                              (kt + 1) * 64)
            CP_COMMIT();
        }
        GEMM_KSTEP64(0)
        GEMM_KSTEP64(1)
        GEMM_KSTEP64(2)
        GEMM_KSTEP64(3)
    }

    // epilogue: + bias, * scale(Q), convert, scatter to (b,h,n,d)
    const int r0 = lane >> 2, cq = (lane & 3) * 2;
    #pragma unroll
    for (int mi = 0; mi < 4; mi++) {
        #pragma unroll
        for (int ni = 0; ni < 4; ni++) {
            int col = n0 + wn + ni * 8 + cq;
            float b0 = bias[col], b1 = bias[col + 1];
            int hh = col >> 6, d = col & 63;
            #pragma unroll
            for (int half = 0; half < 2; half++) {
                int row = m0 + wm + mi * 16 + r0 + half * 8;
                float v0 = (c[mi][ni][half * 2 + 0] + b0) * scale;
                float v1 = (c[mi][ni][half * 2 + 1] + b1) * scale;
                int bb = row >> 11, n = row & (NSEQ - 1);
                size_t idx = (((size_t)(bb * NH + hh)) * NSEQ + n) * HD + d;
                unsigned pv = pack_h2(v0, v1);
                if (z == 0)      *(unsigned*)&gQ[idx] = pv;
                else if (z == 1) *(unsigned*)&gK[idx] = pv;
                else             *(unsigned*)&gV[idx] = pv;
            }
        }
    }
}

// ---------------- output projection GEMM (1-term fp16, BK=64) --------------
__global__ __launch_bounds__(256, 2) void gemm_out(
    const float* __restrict__ bo, float* __restrict__ out)
{
    extern __shared__ __half gsm[];
    __half* sA = gsm;
    __half* sB = gsm + 2 * GTILE;

    const __half* Wp = gW + 3 * WELEM;

    const int tid = threadIdx.x, lane = tid & 31, warp = tid >> 5;
    const int m0 = blockIdx.y * 128, n0 = blockIdx.x * 128;
    const int wm = (warp & 1) * 64, wn = (warp >> 1) * 32;

    const __half* gA = gO + (size_t)m0 * DM;
    const __half* gB = Wp + (size_t)n0 * DM;

    float c[4][4][4];
    #pragma unroll
    for (int i = 0; i < 4; i++)
        #pragma unroll
        for (int j = 0; j < 4; j++)
            #pragma unroll
            for (int r = 0; r < 4; r++) c[i][j][r] = 0.0f;

    GEMM_LOAD_STAGE64(sA, sB, 0)
    CP_COMMIT();

    const int ar = lane & 15, achk = lane >> 4;
    const int br = lane & 7,  bchk = (lane >> 3) & 1;

    for (int kt = 0; kt < 16; kt++) {
        const int st = kt & 1;
        CP_WAIT0();
        __syncthreads();
        if (kt < 15) {
            GEMM_LOAD_STAGE64(sA + (st ^ 1) * GTILE, sB + (st ^ 1) * GTILE,
                              (kt + 1) * 64)
            CP_COMMIT();
        }
        GEMM_KSTEP64(0)
        GEMM_KSTEP64(1)
        GEMM_KSTEP64(2)
        GEMM_KSTEP64(3)
    }

    const int r0 = lane >> 2, cq = (lane & 3) * 2;
    #pragma unroll
    for (int mi = 0; mi < 4; mi++) {
        #pragma unroll
        for (int ni = 0; ni < 4; ni++) {
            int col = n0 + wn + ni * 8 + cq;
            float b0 = bo[col], b1 = bo[col + 1];
            #pragma unroll
            for (int half = 0; half < 2; half++) {
                int row = m0 + wm + mi * 16 + r0 + half * 8;
                float2 v = make_float2(c[mi][ni][half * 2 + 0] + b0,
                                       c[mi][ni][half * 2 + 1] + b1);
                *(float2*)&out[(size_t)row * DM + col] = v;
            }
        }
    }
}

// ---------------- flash attention -------------------------------------------
// S: Q fp16 x K fp16 (1 MMA). PV: P fp16 x V fp16 (1 MMA). ex2-domain softmax.
// KV stages of 128 keys (two 64-key subtiles) -> 16 sync intervals.
// smem: Q 128x64 + 2 stages x (K,V 128x64) = 81,920 B -> 2 CTAs/SM.
#define QTSZ    (128*64)             // elems per Q tile
#define KVTSZ2  (128*64)             // elems per K or V tile (128 keys)
#define KVSTG2  (2*KVTSZ2)           // elems per KV stage [K, V]
#define FLASH_SMEM ((QTSZ + 2*KVSTG2) * 2)   // bytes = 81920

__global__ __launch_bounds__(256, 2) void flash()
{
    extern __shared__ __half sm[];
    __half* sQ  = sm;                 // [128x64] swizzled
    __half* sKV = sm + QTSZ;          // [stage][K(128x64),V(128x64)]

    const int tid = threadIdx.x, lane = tid & 31, warp = tid >> 5;
    const int bh = blockIdx.y, q0 = blockIdx.x * 128;
    const size_t base = (size_t)bh * NSEQ * HD;

    // Q tile: 1024 chunks; 4 per thread
    #pragma unroll
    for (int u = 0; u < 4; u++) {
        int id = tid + u * 256;
        int r = id >> 3, c8 = id & 7;
        cp16(&sQ[swz64(r, c8)], gQ + base + (size_t)(q0 + r) * HD + c8 * 8);
    }
    // KV stage 0: K+V 128 keys = 2048 chunks; 8 per thread
    #pragma unroll
    for (int u = 0; u < 8; u++) {
        int id = tid + u * 256;
        int t = id >> 10, rem = id & 1023;
        int r = rem >> 3, c8 = rem & 7;
        size_t g = base + (size_t)r * HD + c8 * 8;
        const void* src = (t == 0) ? (const void*)(gK + g)
                                   : (const void*)(gV + g);
        cp16(&sKV[t * KVTSZ2 + swz64(r, c8)], src);
    }
    CP_COMMIT();

    float o[8][4];
    #pragma unroll
    for (int i = 0; i < 8; i++)
        #pragma unroll
        for (int j = 0; j < 4; j++) o[i][j] = 0.0f;
    float mr0 = -1e30f, mr1 = -1e30f, lr0 = 0.0f, lr1 = 0.0f;

    const int ar = lane & 15;
    const int achk = lane >> 4;          // A-operand chunk half
    const int br = lane & 7;
    const int bchk = (lane >> 3) & 1;    // B-operand chunk half

    for (int kt = 0; kt < NSEQ / 128; kt++) {
        const int st = kt & 1;
        CP_WAIT0();
        __syncthreads();
        if (kt < NSEQ / 128 - 1) {
            __half* d = sKV + (st ^ 1) * KVSTG2;
            size_t kb = base + (size_t)(kt + 1) * 128 * HD;
            #pragma unroll
            for (int u = 0; u < 8; u++) {
                int id = tid + u * 256;
                int t = id >> 10, rem = id & 1023;
                int r = rem >> 3, c8 = rem & 7;
                size_t g = kb + (size_t)r * HD + c8 * 8;
                const void* src = (t == 0) ? (const void*)(gK + g)
                                           : (const void*)(gV + g);
                cp16(&d[t * KVTSZ2 + swz64(r, c8)], src);
            }
            CP_COMMIT();
        }

        #pragma unroll
        for (int sub = 0; sub < 2; sub++) {
            const __half* Ks = sKV + st * KVSTG2 + sub * (64 * 64);
            const __half* Vs = sKV + st * KVSTG2 + KVTSZ2 + sub * (64 * 64);

            float s[8][4];
            #pragma unroll
            for (int i = 0; i < 8; i++)
                #pragma unroll
                for (int j = 0; j < 4; j++) s[i][j] = 0.0f;

            // S = Q.K^T — 1 term, term-major over ni-quads
            #pragma unroll
            for (int kk = 0; kk < 4; kk++) {
                unsigned ah[4];
                int arow = warp * 16 + ar;
                int aoff = swz64(arow, kk * 2 + achk);
                ldm_x4(ah[0], ah[1], ah[2], ah[3], &sQ[aoff]);
                #pragma unroll
                for (int nh = 0; nh < 2; nh++) {
                    unsigned kb4[4][2];
                    #pragma unroll
                    for (int nq = 0; nq < 4; nq++) {
                        int krow = (nh * 4 + nq) * 8 + br;
                        int koff = swz64(krow, kk * 2 + bchk);
                        ldm_x2(kb4[nq][0], kb4[nq][1], &Ks[koff]);
                    }
                    #pragma unroll
                    for (int nq = 0; nq < 4; nq++)
                        mma16816h(s[nh * 4 + nq], ah[0], ah[1], ah[2], ah[3],
                                  kb4[nq][0], kb4[nq][1]);
                }
            }

            float mx0 = -1e30f, mx1 = -1e30f;
            #pragma unroll
            for (int ni = 0; ni < 8; ni++) {
                mx0 = fmaxf(mx0, fmaxf(s[ni][0], s[ni][1]));
                mx1 = fmaxf(mx1, fmaxf(s[ni][2], s[ni][3]));
            }
            mx0 = fmaxf(mx0, __shfl_xor_sync(0xffffffffu, mx0, 1));
            mx0 = fmaxf(mx0, __shfl_xor_sync(0xffffffffu, mx0, 2));
            mx1 = fmaxf(mx1, __shfl_xor_sync(0xffffffffu, mx1, 1));
            mx1 = fmaxf(mx1, __shfl_xor_sync(0xffffffffu, mx1, 2));

            float nm0 = fmaxf(mr0, mx0), nm1 = fmaxf(mr1, mx1);
            float cr0 = ex2a(mr0 - nm0), cr1 = ex2a(mr1 - nm1);
            mr0 = nm0; mr1 = nm1;

            float sum0 = 0.0f, sum1 = 0.0f;
            #pragma unroll
            for (int ni = 0; ni < 8; ni++) {
                s[ni][0] = ex2a(s[ni][0] - nm0);
                s[ni][1] = ex2a(s[ni][1] - nm0);
                s[ni][2] = ex2a(s[ni][2] - nm1);
                s[ni][3] = ex2a(s[ni][3] - nm1);
                sum0 += s[ni][0] + s[ni][1];
                sum1 += s[ni][2] + s[ni][3];
            }
            sum0 += __shfl_xor_sync(0xffffffffu, sum0, 1);
            sum0 += __shfl_xor_sync(0xffffffffu, sum0, 2);
            sum1 += __shfl_xor_sync(0xffffffffu, sum1, 1);
            sum1 += __shfl_xor_sync(0xffffffffu, sum1, 2);
            lr0 = lr0 * cr0 + sum0;
            lr1 = lr1 * cr1 + sum1;
            #pragma unroll
            for (int dj = 0; dj < 8; dj++) {
                o[dj][0] *= cr0; o[dj][1] *= cr0;
                o[dj][2] *= cr1; o[dj][3] *= cr1;
            }

            // O += P(fp16) . V(fp16) — term-major over dj-quads
            #pragma unroll
            for (int kk = 0; kk < 4; kk++) {
                unsigned p0 = pack_h2(s[2*kk][0],   s[2*kk][1]);
                unsigned p1 = pack_h2(s[2*kk][2],   s[2*kk][3]);
                unsigned p2 = pack_h2(s[2*kk+1][0], s[2*kk+1][1]);
                unsigned p3 = pack_h2(s[2*kk+1][2], s[2*kk+1][3]);
                int vrow = kk * 16 + ar;
                #pragma unroll
                for (int dh = 0; dh < 2; dh++) {
                    unsigned vb4[4][2];
                    #pragma unroll
                    for (int dq = 0; dq < 4; dq++) {
                        int voff = swz64(vrow, dh * 4 + dq);
                        ldm_x2t(vb4[dq][0], vb4[dq][1], &Vs[voff]);
                    }
                    #pragma unroll
                    for (int dq = 0; dq < 4; dq++)
                        mma16816h(o[dh * 4 + dq], p0, p1, p2, p3,
                                  vb4[dq][0], vb4[dq][1]);
                }
            }
        }
    }

    const int b = bh >> 4, h = bh & 15;
    const int row0 = q0 + warp * 16 + (lane >> 2);
    const float inv0 = 1.0f / lr0, inv1 = 1.0f / lr1;
    const size_t rb = ((size_t)(b * NSEQ) + row0) * DM + h * HD;
    #pragma unroll
    for (int dj = 0; dj < 8; dj++) {
        int d = dj * 8 + (lane & 3) * 2;
        *(unsigned*)&gO[rb + d] = pack_h2(o[dj][0] * inv0, o[dj][1] * inv0);
        *(unsigned*)&gO[rb + (size_t)8 * DM + d] =
            pack_h2(o[dj][2] * inv1, o[dj][3] * inv1);
    }
}

// ---------------------------------------------------------------------------
extern "C" void kernel_launch(void* const* d_in, const int* in_sizes, int n_in,
                              void* d_out, int out_size)
{
    (void)in_sizes; (void)n_in; (void)out_size;
    const float* queries = (const float*)d_in[0];
    const float* keys    = (const float*)d_in[1];
    const float* values  = (const float*)d_in[2];
    const float* Wq = (const float*)d_in[3];
    const float* bq = (const float*)d_in[4];
    const float* Wk = (const float*)d_in[5];
    const float* bk = (const float*)d_in[6];
    const float* Wv = (const float*)d_in[7];
    const float* bv = (const float*)d_in[8];
    const float* Wo = (const float*)d_in[9];
    const float* bo = (const float*)d_in[10];
    float* out = (float*)d_out;

    cudaFuncSetAttribute(flash, cudaFuncAttributeMaxDynamicSharedMemorySize,
                         FLASH_SMEM);
    cudaFuncSetAttribute(gemm_qkv, cudaFuncAttributeMaxDynamicSharedMemorySize,
                         GSMEM);
    cudaFuncSetAttribute(gemm_out, cudaFuncAttributeMaxDynamicSharedMemorySize,
                         GSMEM);

    // fp32 -> fp16 (single launch)
    split_all<<<2048, 256>>>(queries, keys, values, Wq, Wk, Wv, Wo);

    // QKV projections
    gemm_qkv<<<dim3(DM / 128, MROWS / 128, 3), 256, GSMEM>>>(bq, bk, bv);

    // attention
    flash<<<dim3(NSEQ / 128, NB * NH), 256, FLASH_SMEM>>>();

    // output projection
    gemm_out<<<dim3(DM / 128, MROWS / 128), 256, GSMEM>>>(bo, out);
}

// round 16
// speedup vs baseline: 1.0691x; 1.0186x over previous
#include <cuda_runtime.h>
#include <cuda_bf16.h>
#include <cuda_fp16.h>
#include <math.h>
#include <stdint.h>

#define DM   1024
#define NSEQ 2048
#define NB   2
#define NH   16
#define HD   64
#define MROWS (NB*NSEQ)          // 4096
#define NELEM ((size_t)MROWS*DM) // 4,194,304
#define WELEM ((size_t)DM*DM)    // 1,048,576

// ---------------- scratch (__device__ globals; no allocations) -------------
__device__ __half gX[3*NELEM];                // inputs q,k,v single fp16
__device__ __half gW[4*WELEM];                // weights single fp16
__device__ __half gQ[NELEM];                  // (b,h,n,d), Q pre-scaled by 0.125*log2e
__device__ __half gK[NELEM];                  // K single fp16
__device__ __half gV[NELEM];                  // V single fp16
__device__ __half gO[NELEM];                  // attn out (b*n, h*d), single

// ---------------- PTX helpers ---------------------------------------------
__device__ __forceinline__ void mma16816h(float* c,
    unsigned a0, unsigned a1, unsigned a2, unsigned a3,
    unsigned b0, unsigned b1)
{
    asm volatile(
        "mma.sync.aligned.m16n8k16.row.col.f32.f16.f16.f32 "
        "{%0,%1,%2,%3},{%4,%5,%6,%7},{%8,%9},{%0,%1,%2,%3};"
        : "+f"(c[0]), "+f"(c[1]), "+f"(c[2]), "+f"(c[3])
        : "r"(a0), "r"(a1), "r"(a2), "r"(a3), "r"(b0), "r"(b1));
}

__device__ __forceinline__ void ldm_x4(unsigned& r0, unsigned& r1,
                                       unsigned& r2, unsigned& r3,
                                       const void* p)
{
    unsigned a = (unsigned)__cvta_generic_to_shared(p);
    asm volatile("ldmatrix.sync.aligned.m8n8.x4.shared.b16 {%0,%1,%2,%3},[%4];"
                 : "=r"(r0), "=r"(r1), "=r"(r2), "=r"(r3) : "r"(a));
}

__device__ __forceinline__ void ldm_x2(unsigned& r0, unsigned& r1, const void* p)
{
    unsigned a = (unsigned)__cvta_generic_to_shared(p);
    asm volatile("ldmatrix.sync.aligned.m8n8.x2.shared.b16 {%0,%1},[%2];"
                 : "=r"(r0), "=r"(r1) : "r"(a));
}

__device__ __forceinline__ void ldm_x2t(unsigned& r0, unsigned& r1, const void* p)
{
    unsigned a = (unsigned)__cvta_generic_to_shared(p);
    asm volatile("ldmatrix.sync.aligned.m8n8.x2.trans.shared.b16 {%0,%1},[%2];"
                 : "=r"(r0), "=r"(r1) : "r"(a));
}

__device__ __forceinline__ void cp16(void* dst, const void* src)
{
    unsigned d = (unsigned)__cvta_generic_to_shared(dst);
    asm volatile("cp.async.cg.shared.global [%0], [%1], 16;" :: "r"(d), "l"(src));
}
#define CP_COMMIT() asm volatile("cp.async.commit_group;")
#define CP_WAIT0()  asm volatile("cp.async.wait_group 0;")

__device__ __forceinline__ unsigned pack_h2(float x, float y)
{
    __half2 p = __floats2half2_rn(x, y);
    return *(unsigned*)&p;
}

__device__ __forceinline__ float ex2a(float x)
{
    float r;
    asm("ex2.approx.f32 %0, %1;" : "=f"(r) : "f"(x));
    return r;
}

__device__ __forceinline__ float4 ldg_cs4(const float4* p)
{
    float4 v;
    asm("ld.global.cs.v4.f32 {%0,%1,%2,%3}, [%4];"
        : "=f"(v.x), "=f"(v.y), "=f"(v.z), "=f"(v.w) : "l"(p));
    return v;
}

__device__ __forceinline__ void stg_cs2(uint2* p, uint2 v)
{
    asm volatile("st.global.cs.v2.u32 [%0], {%1,%2};"
                 :: "l"(p), "r"(v.x), "r"(v.y));
}

// 16B-chunk XOR swizzle for 64-col fp16 tiles (row*64 elems + chunk^row&7)
__device__ __forceinline__ int swz64(int r, int c8)
{
    return r * 64 + ((c8 ^ (r & 7)) * 8);
}

// ---------------- merged fp32 -> fp16 conversion (single launch) -----------
#define NF4_IN (NELEM >> 2)   // 2^20 float4 per input tensor
#define NF4_W  (WELEM >> 2)   // 2^18 float4 per weight tensor
#define NF4_TOT (3*NF4_IN + 4*NF4_W)

__global__ void split_all(const float* __restrict__ q, const float* __restrict__ k,
                          const float* __restrict__ v, const float* __restrict__ wq,
                          const float* __restrict__ wk, const float* __restrict__ wv,
                          const float* __restrict__ wo)
{
    for (size_t i = blockIdx.x * blockDim.x + threadIdx.x; i < NF4_TOT;
         i += (size_t)gridDim.x * blockDim.x) {
        const float* src;
        __half* h;
        size_t off;
        if (i < 3*NF4_IN) {
            int slot = (int)(i >> 20);
            off = i & (NF4_IN - 1);
            src = (slot == 0) ? q : (slot == 1) ? k : v;
            h = gX + (size_t)slot * NELEM;
        } else {
            size_t j = i - 3*NF4_IN;
            int slot = (int)(j >> 18);
            off = j & (NF4_W - 1);
            src = (slot == 0) ? wq : (slot == 1) ? wk : (slot == 2) ? wv : wo;
            h = gW + (size_t)slot * WELEM;
        }
        float4 val = ldg_cs4((const float4*)src + off);
        stg_cs2((uint2*)h + off, make_uint2(pack_h2(val.x, val.y),
                                            pack_h2(val.z, val.w)));
    }
}

// ---------------- GEMM: BK=64, swizzled 64-col tiles, dynamic smem ---------
#define GTILE   (128*64)                 // elems per tile
#define GSMEM   (4*GTILE*2)              // bytes = 65536 (2 stages x 2 tiles)

// stage load: A,B tiles 128 rows x 8 chunks; 2048 chunks total, 8 per thread
#define GEMM_LOAD_STAGE64(dstA, dstB, koff)                                   \
    {                                                                         \
        _Pragma("unroll")                                                     \
        for (int u = 0; u < 4; u++) {                                         \
            int id = tid + u * 256;                                           \
            int r = id >> 3, c8 = id & 7;                                     \
            int sw = swz64(r, c8);                                            \
            cp16(&(dstA)[sw], gA + (size_t)r * DM + (koff) + c8 * 8);         \
            cp16(&(dstB)[sw], gB + (size_t)r * DM + (koff) + c8 * 8);         \
        }                                                                     \
    }

// one k-step (16 wide) = 16 MMAs; kk in 0..3
#define GEMM_KSTEP64(kk)                                                      \
    {                                                                         \
        unsigned bf[4][2];                                                    \
        _Pragma("unroll")                                                     \
        for (int ni = 0; ni < 4; ni++) {                                      \
            int off = swz64(wn + ni * 8 + br, (kk) * 2 + bchk);               \
            ldm_x2(bf[ni][0], bf[ni][1], &sB[st * GTILE + off]);              \
        }                                                                     \
        _Pragma("unroll")                                                     \
        for (int mp = 0; mp < 2; mp++) {                                      \
            unsigned ah[2][4];                                                \
            _Pragma("unroll")                                                 \
            for (int q = 0; q < 2; q++) {                                     \
                int off = swz64(wm + (mp * 2 + q) * 16 + ar, (kk) * 2 + achk);\
                ldm_x4(ah[q][0], ah[q][1], ah[q][2], ah[q][3],                \
                       &sA[st * GTILE + off]);                                \
            }                                                                 \
            _Pragma("unroll")                                                 \
            for (int q = 0; q < 2; q++)                                       \
                _Pragma("unroll")                                             \
                for (int ni = 0; ni < 4; ni++)                                \
                    mma16816h(c[mp * 2 + q][ni], ah[q][0], ah[q][1],          \
                              ah[q][2], ah[q][3], bf[ni][0], bf[ni][1]);      \
        }                                                                     \
    }

// ---------------- QKV projection GEMM (1-term fp16, BK=64) -----------------
__global__ __launch_bounds__(256, 2) void gemm_qkv(
    const float* __restrict__ bq, const float* __restrict__ bk,
    const float* __restrict__ bv)
{
    extern __shared__ __half gsm[];
    __half* sA = gsm;                // [2][GTILE]
    __half* sB = gsm + 2 * GTILE;    // [2][GTILE]

    const int z = blockIdx.z;
    const __half* Xp = gX + (size_t)z * NELEM;
    const __half* Wp = gW + (size_t)z * WELEM;
    const float* bias = (z == 0) ? bq : (z == 1) ? bk : bv;
    // Q scale folds softmax 1/sqrt(64) AND log2(e) for the ex2-domain softmax
    const float scale = (z == 0) ? 0.125f * 1.44269504f : 1.0f;

    const int tid = threadIdx.x, lane = tid & 31, warp = tid >> 5;
    const int m0 = blockIdx.y * 128, n0 = blockIdx.x * 128;
    const int wm = (warp & 1) * 64, wn = (warp >> 1) * 32;

    const __half* gA = Xp + (size_t)m0 * DM;
    const __half* gB = Wp + (size_t)n0 * DM;

    float c[4][4][4];
    #pragma unroll
    for (int i = 0; i < 4; i++)
        #pragma unroll
        for (int j = 0; j < 4; j++)
            #pragma unroll
            for (int r = 0; r < 4; r++) c[i][j][r] = 0.0f;

    GEMM_LOAD_STAGE64(sA, sB, 0)
    CP_COMMIT();

    const int ar = lane & 15, achk = lane >> 4;
    const int br = lane & 7,  bchk = (lane >> 3) & 1;

    for (int kt = 0; kt < 16; kt++) {
        const int st = kt & 1;
        CP_WAIT0();
        __syncthreads();
        if (kt < 15) {
            GEMM_LOAD_STAGE64(sA + (st ^ 1) * GTILE, sB + (st ^ 1) * GTILE,
                              (kt + 1) * 64)
            CP_COMMIT();
        }
        GEMM_KSTEP64(0)
        GEMM_KSTEP64(1)
        GEMM_KSTEP64(2)
        GEMM_KSTEP64(3)
    }

    // epilogue: + bias, * scale(Q), convert, scatter to (b,h,n,d)
    const int r0 = lane >> 2, cq = (lane & 3) * 2;
    #pragma unroll
    for (int mi = 0; mi < 4; mi++) {
        #pragma unroll
        for (int ni = 0; ni < 4; ni++) {
            int col = n0 + wn + ni * 8 + cq;
            float b0 = bias[col], b1 = bias[col + 1];
            int hh = col >> 6, d = col & 63;
            #pragma unroll
            for (int half = 0; half < 2; half++) {
                int row = m0 + wm + mi * 16 + r0 + half * 8;
                float v0 = (c[mi][ni][half * 2 + 0] + b0) * scale;
                float v1 = (c[mi][ni][half * 2 + 1] + b1) * scale;
                int bb = row >> 11, n = row & (NSEQ - 1);
                size_t idx = (((size_t)(bb * NH + hh)) * NSEQ + n) * HD + d;
                unsigned pv = pack_h2(v0, v1);
                if (z == 0)      *(unsigned*)&gQ[idx] = pv;
                else if (z == 1) *(unsigned*)&gK[idx] = pv;
                else             *(unsigned*)&gV[idx] = pv;
            }
        }
    }
}

// ---------------- output projection GEMM (1-term fp16, BK=64) --------------
__global__ __launch_bounds__(256, 2) void gemm_out(
    const float* __restrict__ bo, float* __restrict__ out)
{
    extern __shared__ __half gsm[];
    __half* sA = gsm;
    __half* sB = gsm + 2 * GTILE;

    const __half* Wp = gW + 3 * WELEM;

    const int tid = threadIdx.x, lane = tid & 31, warp = tid >> 5;
    const int m0 = blockIdx.y * 128, n0 = blockIdx.x * 128;
    const int wm = (warp & 1) * 64, wn = (warp >> 1) * 32;

    const __half* gA = gO + (size_t)m0 * DM;
    const __half* gB = Wp + (size_t)n0 * DM;

    float c[4][4][4];
    #pragma unroll
    for (int i = 0; i < 4; i++)
        #pragma unroll
        for (int j = 0; j < 4; j++)
            #pragma unroll
            for (int r = 0; r < 4; r++) c[i][j][r] = 0.0f;

    GEMM_LOAD_STAGE64(sA, sB, 0)
    CP_COMMIT();

    const int ar = lane & 15, achk = lane >> 4;
    const int br = lane & 7,  bchk = (lane >> 3) & 1;

    for (int kt = 0; kt < 16; kt++) {
        const int st = kt & 1;
        CP_WAIT0();
        __syncthreads();
        if (kt < 15) {
            GEMM_LOAD_STAGE64(sA + (st ^ 1) * GTILE, sB + (st ^ 1) * GTILE,
                              (kt + 1) * 64)
            CP_COMMIT();
        }
        GEMM_KSTEP64(0)
        GEMM_KSTEP64(1)
        GEMM_KSTEP64(2)
        GEMM_KSTEP64(3)
    }

    const int r0 = lane >> 2, cq = (lane & 3) * 2;
    #pragma unroll
    for (int mi = 0; mi < 4; mi++) {
        #pragma unroll
        for (int ni = 0; ni < 4; ni++) {
            int col = n0 + wn + ni * 8 + cq;
            float b0 = bo[col], b1 = bo[col + 1];
            #pragma unroll
            for (int half = 0; half < 2; half++) {
                int row = m0 + wm + mi * 16 + r0 + half * 8;
                float2 v = make_float2(c[mi][ni][half * 2 + 0] + b0,
                                       c[mi][ni][half * 2 + 1] + b1);
                *(float2*)&out[(size_t)row * DM + col] = v;
            }
        }
    }
}

// ---------------- flash attention -------------------------------------------
// S: Q fp16 x K fp16 (1 MMA). PV: P fp16 x V fp16 (1 MMA). ex2-domain softmax.
// Q fragments register-resident (loaded once). 128-key KV stages.
// smem: Q 128x64 + 2 stages x (K,V 128x64) = 81,920 B -> 2 CTAs/SM.
#define QTSZ    (128*64)             // elems per Q tile
#define KVTSZ2  (128*64)             // elems per K or V tile (128 keys)
#define KVSTG2  (2*KVTSZ2)           // elems per KV stage [K, V]
#define FLASH_SMEM ((QTSZ + 2*KVSTG2) * 2)   // bytes = 81920

__global__ __launch_bounds__(256, 2) void flash()
{
    extern __shared__ __half sm[];
    __half* sQ  = sm;                 // [128x64] swizzled
    __half* sKV = sm + QTSZ;          // [stage][K(128x64),V(128x64)]

    const int tid = threadIdx.x, lane = tid & 31, warp = tid >> 5;
    const int bh = blockIdx.y, q0 = blockIdx.x * 128;
    const size_t base = (size_t)bh * NSEQ * HD;

    // Q tile: 1024 chunks; 4 per thread
    #pragma unroll
    for (int u = 0; u < 4; u++) {
        int id = tid + u * 256;
        int r = id >> 3, c8 = id & 7;
        cp16(&sQ[swz64(r, c8)], gQ + base + (size_t)(q0 + r) * HD + c8 * 8);
    }
    // KV stage 0: K+V 128 keys = 2048 chunks; 8 per thread
    #pragma unroll
    for (int u = 0; u < 8; u++) {
        int id = tid + u * 256;
        int t = id >> 10, rem = id & 1023;
        int r = rem >> 3, c8 = rem & 7;
        size_t g = base + (size_t)r * HD + c8 * 8;
        const void* src = (t == 0) ? (const void*)(gK + g)
                                   : (const void*)(gV + g);
        cp16(&sKV[t * KVTSZ2 + swz64(r, c8)], src);
    }
    CP_COMMIT();

    float o[8][4];
    #pragma unroll
    for (int i = 0; i < 8; i++)
        #pragma unroll
        for (int j = 0; j < 4; j++) o[i][j] = 0.0f;
    float mr0 = -1e30f, mr1 = -1e30f, lr0 = 0.0f, lr1 = 0.0f;

    const int ar = lane & 15;
    const int achk = lane >> 4;          // A-operand chunk half
    const int br = lane & 7;
    const int bchk = (lane >> 3) & 1;    // B-operand chunk half

    unsigned aq[4][4];                   // Q frags, loaded once at kt==0

    for (int kt = 0; kt < NSEQ / 128; kt++) {
        const int st = kt & 1;
        CP_WAIT0();
        __syncthreads();
        if (kt == 0) {
            // hoist Q fragments into registers (invariant across tiles)
            #pragma unroll
            for (int kk = 0; kk < 4; kk++) {
                int aoff = swz64(warp * 16 + ar, kk * 2 + achk);
                ldm_x4(aq[kk][0], aq[kk][1], aq[kk][2], aq[kk][3], &sQ[aoff]);
            }
        }
        if (kt < NSEQ / 128 - 1) {
            __half* d = sKV + (st ^ 1) * KVSTG2;
            size_t kb = base + (size_t)(kt + 1) * 128 * HD;
            #pragma unroll
            for (int u = 0; u < 8; u++) {
                int id = tid + u * 256;
                int t = id >> 10, rem = id & 1023;
                int r = rem >> 3, c8 = rem & 7;
                size_t g = kb + (size_t)r * HD + c8 * 8;
                const void* src = (t == 0) ? (const void*)(gK + g)
                                           : (const void*)(gV + g);
                cp16(&d[t * KVTSZ2 + swz64(r, c8)], src);
            }
            CP_COMMIT();
        }

        #pragma unroll
        for (int sub = 0; sub < 2; sub++) {
            const __half* Ks = sKV + st * KVSTG2 + sub * (64 * 64);
            const __half* Vs = sKV + st * KVSTG2 + KVTSZ2 + sub * (64 * 64);

            float s[8][4];
            #pragma unroll
            for (int i = 0; i < 8; i++)
                #pragma unroll
                for (int j = 0; j < 4; j++) s[i][j] = 0.0f;

            // S = Q.K^T — 1 term, Q frags from registers
            #pragma unroll
            for (int kk = 0; kk < 4; kk++) {
                #pragma unroll
                for (int nh = 0; nh < 2; nh++) {
                    unsigned kb4[4][2];
                    #pragma unroll
                    for (int nq = 0; nq < 4; nq++) {
                        int krow = (nh * 4 + nq) * 8 + br;
                        int koff = swz64(krow, kk * 2 + bchk);
                        ldm_x2(kb4[nq][0], kb4[nq][1], &Ks[koff]);
                    }
                    #pragma unroll
                    for (int nq = 0; nq < 4; nq++)
                        mma16816h(s[nh * 4 + nq], aq[kk][0], aq[kk][1],
                                  aq[kk][2], aq[kk][3],
                                  kb4[nq][0], kb4[nq][1]);
                }
            }

            float mx0 = -1e30f, mx1 = -1e30f;
            #pragma unroll
            for (int ni = 0; ni < 8; ni++) {
                mx0 = fmaxf(mx0, fmaxf(s[ni][0], s[ni][1]));
                mx1 = fmaxf(mx1, fmaxf(s[ni][2], s[ni][3]));
            }
            mx0 = fmaxf(mx0, __shfl_xor_sync(0xffffffffu, mx0, 1));
            mx0 = fmaxf(mx0, __shfl_xor_sync(0xffffffffu, mx0, 2));
            mx1 = fmaxf(mx1, __shfl_xor_sync(0xffffffffu, mx1, 1));
            mx1 = fmaxf(mx1, __shfl_xor_sync(0xffffffffu, mx1, 2));

            float nm0 = fmaxf(mr0, mx0), nm1 = fmaxf(mr1, mx1);
            float cr0 = ex2a(mr0 - nm0), cr1 = ex2a(mr1 - nm1);
            mr0 = nm0; mr1 = nm1;

            float sum0 = 0.0f, sum1 = 0.0f;
            #pragma unroll
            for (int ni = 0; ni < 8; ni++) {
                s[ni][0] = ex2a(s[ni][0] - nm0);
                s[ni][1] = ex2a(s[ni][1] - nm0);
                s[ni][2] = ex2a(s[ni][2] - nm1);
                s[ni][3] = ex2a(s[ni][3] - nm1);
                sum0 += s[ni][0] + s[ni][1];
                sum1 += s[ni][2] + s[ni][3];
            }
            sum0 += __shfl_xor_sync(0xffffffffu, sum0, 1);
            sum0 += __shfl_xor_sync(0xffffffffu, sum0, 2);
            sum1 += __shfl_xor_sync(0xffffffffu, sum1, 1);
            sum1 += __shfl_xor_sync(0xffffffffu, sum1, 2);
            lr0 = lr0 * cr0 + sum0;
            lr1 = lr1 * cr1 + sum1;
            #pragma unroll
            for (int dj = 0; dj < 8; dj++) {
                o[dj][0] *= cr0; o[dj][1] *= cr0;
                o[dj][2] *= cr1; o[dj][3] *= cr1;
            }

            // O += P(fp16) . V(fp16) — term-major over dj-quads
            #pragma unroll
            for (int kk = 0; kk < 4; kk++) {
                unsigned p0 = pack_h2(s[2*kk][0],   s[2*kk][1]);
                unsigned p1 = pack_h2(s[2*kk][2],   s[2*kk][3]);
                unsigned p2 = pack_h2(s[2*kk+1][0], s[2*kk+1][1]);
                unsigned p3 = pack_h2(s[2*kk+1][2], s[2*kk+1][3]);
                int vrow = kk * 16 + ar;
                #pragma unroll
                for (int dh = 0; dh < 2; dh++) {
                    unsigned vb4[4][2];
                    #pragma unroll
                    for (int dq = 0; dq < 4; dq++) {
                        int voff = swz64(vrow, dh * 4 + dq);
                        ldm_x2t(vb4[dq][0], vb4[dq][1], &Vs[voff]);
                    }
                    #pragma unroll
                    for (int dq = 0; dq < 4; dq++)
                        mma16816h(o[dh * 4 + dq], p0, p1, p2, p3,
                                  vb4[dq][0], vb4[dq][1]);
                }
            }
        }
    }

    const int b = bh >> 4, h = bh & 15;
    const int row0 = q0 + warp * 16 + (lane >> 2);
    const float inv0 = 1.0f / lr0, inv1 = 1.0f / lr1;
    const size_t rb = ((size_t)(b * NSEQ) + row0) * DM + h * HD;
    #pragma unroll
    for (int dj = 0; dj < 8; dj++) {
        int d = dj * 8 + (lane & 3) * 2;
        *(unsigned*)&gO[rb + d] = pack_h2(o[dj][0] * inv0, o[dj][1] * inv0);
        *(unsigned*)&gO[rb + (size_t)8 * DM + d] =
            pack_h2(o[dj][2] * inv1, o[dj][3] * inv1);
    }
}

// ---------------------------------------------------------------------------
extern "C" void kernel_launch(void* const* d_in, const int* in_sizes, int n_in,
                              void* d_out, int out_size)
{
    (void)in_sizes; (void)n_in; (void)out_size;
    const float* queries = (const float*)d_in[0];
    const float* keys    = (const float*)d_in[1];
    const float* values  = (const float*)d_in[2];
    const float* Wq = (const float*)d_in[3];
    const float* bq = (const float*)d_in[4];
    const float* Wk = (const float*)d_in[5];
    const float* bk = (const float*)d_in[6];
    const float* Wv = (const float*)d_in[7];
    const float* bv = (const float*)d_in[8];
    const float* Wo = (const float*)d_in[9];
    const float* bo = (const float*)d_in[10];
    float* out = (float*)d_out;

    cudaFuncSetAttribute(flash, cudaFuncAttributeMaxDynamicSharedMemorySize,
                         FLASH_SMEM);
    cudaFuncSetAttribute(gemm_qkv, cudaFuncAttributeMaxDynamicSharedMemorySize,
                         GSMEM);
    cudaFuncSetAttribute(gemm_out, cudaFuncAttributeMaxDynamicSharedMemorySize,
                         GSMEM);

    // fp32 -> fp16 (single launch, streaming loads/stores)
    split_all<<<4096, 256>>>(queries, keys, values, Wq, Wk, Wv, Wo);

    // QKV projections
    gemm_qkv<<<dim3(DM / 128, MROWS / 128, 3), 256, GSMEM>>>(bq, bk, bv);

    // attention
    flash<<<dim3(NSEQ / 128, NB * NH), 256, FLASH_SMEM>>>();

    // output projection
    gemm_out<<<dim3(DM / 128, MROWS / 128), 256, GSMEM>>>(bo, out);
}

// round 17
// speedup vs baseline: 1.0758x; 1.0063x over previous
#include <cuda_runtime.h>
#include <cuda_bf16.h>
#include <cuda_fp16.h>
#include <math.h>
#include <stdint.h>

#define DM   1024
#define NSEQ 2048
#define NB   2
#define NH   16
#define HD   64
#define MROWS (NB*NSEQ)          // 4096
#define NELEM ((size_t)MROWS*DM) // 4,194,304
#define WELEM ((size_t)DM*DM)    // 1,048,576

// ---------------- scratch (__device__ globals; no allocations) -------------
__device__ __half gX[3*NELEM];                // inputs q,k,v single fp16
__device__ __half gW[4*WELEM];                // weights single fp16
__device__ __half gQ[NELEM];                  // (b,h,n,d), Q pre-scaled by 0.125*log2e
__device__ __half gK[NELEM];                  // K single fp16
__device__ __half gV[NELEM];                  // V single fp16
__device__ __half gO[NELEM];                  // attn out (b*n, h*d), single

// ---------------- PTX helpers ---------------------------------------------
__device__ __forceinline__ void mma16816h(float* c,
    unsigned a0, unsigned a1, unsigned a2, unsigned a3,
    unsigned b0, unsigned b1)
{
    asm volatile(
        "mma.sync.aligned.m16n8k16.row.col.f32.f16.f16.f32 "
        "{%0,%1,%2,%3},{%4,%5,%6,%7},{%8,%9},{%0,%1,%2,%3};"
        : "+f"(c[0]), "+f"(c[1]), "+f"(c[2]), "+f"(c[3])
        : "r"(a0), "r"(a1), "r"(a2), "r"(a3), "r"(b0), "r"(b1));
}

__device__ __forceinline__ void ldm_x4(unsigned& r0, unsigned& r1,
                                       unsigned& r2, unsigned& r3,
                                       const void* p)
{
    unsigned a = (unsigned)__cvta_generic_to_shared(p);
    asm volatile("ldmatrix.sync.aligned.m8n8.x4.shared.b16 {%0,%1,%2,%3},[%4];"
                 : "=r"(r0), "=r"(r1), "=r"(r2), "=r"(r3) : "r"(a));
}

__device__ __forceinline__ void ldm_x2(unsigned& r0, unsigned& r1, const void* p)
{
    unsigned a = (unsigned)__cvta_generic_to_shared(p);
    asm volatile("ldmatrix.sync.aligned.m8n8.x2.shared.b16 {%0,%1},[%2];"
                 : "=r"(r0), "=r"(r1) : "r"(a));
}

__device__ __forceinline__ void ldm_x2t(unsigned& r0, unsigned& r1, const void* p)
{
    unsigned a = (unsigned)__cvta_generic_to_shared(p);
    asm volatile("ldmatrix.sync.aligned.m8n8.x2.trans.shared.b16 {%0,%1},[%2];"
                 : "=r"(r0), "=r"(r1) : "r"(a));
}

__device__ __forceinline__ void cp16(void* dst, const void* src)
{
    unsigned d = (unsigned)__cvta_generic_to_shared(dst);
    asm volatile("cp.async.cg.shared.global [%0], [%1], 16;" :: "r"(d), "l"(src));
}
#define CP_COMMIT() asm volatile("cp.async.commit_group;")
#define CP_WAIT0()  asm volatile("cp.async.wait_group 0;")

__device__ __forceinline__ unsigned pack_h2(float x, float y)
{
    __half2 p = __floats2half2_rn(x, y);
    return *(unsigned*)&p;
}

__device__ __forceinline__ float ex2a(float x)
{
    float r;
    asm("ex2.approx.f32 %0, %1;" : "=f"(r) : "f"(x));
    return r;
}

__device__ __forceinline__ float4 ldg_cs4(const float4* p)
{
    float4 v;
    asm("ld.global.cs.v4.f32 {%0,%1,%2,%3}, [%4];"
        : "=f"(v.x), "=f"(v.y), "=f"(v.z), "=f"(v.w) : "l"(p));
    return v;
}

// 16B-chunk XOR swizzle for 64-col fp16 tiles (row*64 elems + chunk^row&7)
__device__ __forceinline__ int swz64(int r, int c8)
{
    return r * 64 + ((c8 ^ (r & 7)) * 8);
}

// ---------------- merged fp32 -> fp16 conversion (single launch) -----------
// ld.cs on fp32 source (dead after read); DEFAULT stores so the fp16 result
// stays L2-resident for gemm_qkv (gX 25MB + gW 8MB << 126MB L2).
#define NF4_IN (NELEM >> 2)   // 2^20 float4 per input tensor
#define NF4_W  (WELEM >> 2)   // 2^18 float4 per weight tensor
#define NF4_TOT (3*NF4_IN + 4*NF4_W)

__global__ void split_all(const float* __restrict__ q, const float* __restrict__ k,
                          const float* __restrict__ v, const float* __restrict__ wq,
                          const float* __restrict__ wk, const float* __restrict__ wv,
                          const float* __restrict__ wo)
{
    for (size_t i = blockIdx.x * blockDim.x + threadIdx.x; i < NF4_TOT;
         i += (size_t)gridDim.x * blockDim.x) {
        const float* src;
        __half* h;
        size_t off;
        if (i < 3*NF4_IN) {
            int slot = (int)(i >> 20);
            off = i & (NF4_IN - 1);
            src = (slot == 0) ? q : (slot == 1) ? k : v;
            h = gX + (size_t)slot * NELEM;
        } else {
            size_t j = i - 3*NF4_IN;
            int slot = (int)(j >> 18);
            off = j & (NF4_W - 1);
            src = (slot == 0) ? wq : (slot == 1) ? wk : (slot == 2) ? wv : wo;
            h = gW + (size_t)slot * WELEM;
        }
        float4 val = ldg_cs4((const float4*)src + off);
        ((uint2*)h)[off] = make_uint2(pack_h2(val.x, val.y),
                                      pack_h2(val.z, val.w));
    }
}

// ---------------- GEMM: BK=64, swizzled 64-col tiles, dynamic smem ---------
#define GTILE   (128*64)                 // elems per tile
#define GSMEM   (4*GTILE*2)              // bytes = 65536 (2 stages x 2 tiles)

// stage load: A,B tiles 128 rows x 8 chunks; 2048 chunks total, 8 per thread
#define GEMM_LOAD_STAGE64(dstA, dstB, koff)                                   \
    {                                                                         \
        _Pragma("unroll")                                                     \
        for (int u = 0; u < 4; u++) {                                         \
            int id = tid + u * 256;                                           \
            int r = id >> 3, c8 = id & 7;                                     \
            int sw = swz64(r, c8);                                            \
            cp16(&(dstA)[sw], gA + (size_t)r * DM + (koff) + c8 * 8);         \
            cp16(&(dstB)[sw], gB + (size_t)r * DM + (koff) + c8 * 8);         \
        }                                                                     \
    }

// one k-step (16 wide) = 16 MMAs; kk in 0..3
#define GEMM_KSTEP64(kk)                                                      \
    {                                                                         \
        unsigned bf[4][2];                                                    \
        _Pragma("unroll")                                                     \
        for (int ni = 0; ni < 4; ni++) {                                      \
            int off = swz64(wn + ni * 8 + br, (kk) * 2 + bchk);               \
            ldm_x2(bf[ni][0], bf[ni][1], &sB[st * GTILE + off]);              \
        }                                                                     \
        _Pragma("unroll")                                                     \
        for (int mp = 0; mp < 2; mp++) {                                      \
            unsigned ah[2][4];                                                \
            _Pragma("unroll")                                                 \
            for (int q = 0; q < 2; q++) {                                     \
                int off = swz64(wm + (mp * 2 + q) * 16 + ar, (kk) * 2 + achk);\
                ldm_x4(ah[q][0], ah[q][1], ah[q][2], ah[q][3],                \
                       &sA[st * GTILE + off]);                                \
            }                                                                 \
            _Pragma("unroll")                                                 \
            for (int q = 0; q < 2; q++)                                       \
                _Pragma("unroll")                                             \
                for (int ni = 0; ni < 4; ni++)                                \
                    mma16816h(c[mp * 2 + q][ni], ah[q][0], ah[q][1],          \
                              ah[q][2], ah[q][3], bf[ni][0], bf[ni][1]);      \
        }                                                                     \
    }

// ---------------- QKV projection GEMM (1-term fp16, BK=64) -----------------
__global__ __launch_bounds__(256, 2) void gemm_qkv(
    const float* __restrict__ bq, const float* __restrict__ bk,
    const float* __restrict__ bv)
{
    extern __shared__ __half gsm[];
    __half* sA = gsm;                // [2][GTILE]
    __half* sB = gsm + 2 * GTILE;    // [2][GTILE]

    const int z = blockIdx.z;
    const __half* Xp = gX + (size_t)z * NELEM;
    const __half* Wp = gW + (size_t)z * WELEM;
    const float* bias = (z == 0) ? bq : (z == 1) ? bk : bv;
    // Q scale folds softmax 1/sqrt(64) AND log2(e) for the ex2-domain softmax
    const float scale = (z == 0) ? 0.125f * 1.44269504f : 1.0f;

    const int tid = threadIdx.x, lane = tid & 31, warp = tid >> 5;
    const int m0 = blockIdx.y * 128, n0 = blockIdx.x * 128;
    const int wm = (warp & 1) * 64, wn = (warp >> 1) * 32;

    const __half* gA = Xp + (size_t)m0 * DM;
    const __half* gB = Wp + (size_t)n0 * DM;

    float c[4][4][4];
    #pragma unroll
    for (int i = 0; i < 4; i++)
        #pragma unroll
        for (int j = 0; j < 4; j++)
            #pragma unroll
            for (int r = 0; r < 4; r++) c[i][j][r] = 0.0f;

    GEMM_LOAD_STAGE64(sA, sB, 0)
    CP_COMMIT();

    const int ar = lane & 15, achk = lane >> 4;
    const int br = lane & 7,  bchk = (lane >> 3) & 1;

    for (int kt = 0; kt < 16; kt++) {
        const int st = kt & 1;
        CP_WAIT0();
        __syncthreads();
        if (kt < 15) {
            GEMM_LOAD_STAGE64(sA + (st ^ 1) * GTILE, sB + (st ^ 1) * GTILE,
                              (kt + 1) * 64)
            CP_COMMIT();
        }
        GEMM_KSTEP64(0)
        GEMM_KSTEP64(1)
        GEMM_KSTEP64(2)
        GEMM_KSTEP64(3)
    }

    // epilogue: + bias, * scale(Q), convert, scatter to (b,h,n,d)
    const int r0 = lane >> 2, cq = (lane & 3) * 2;
    #pragma unroll
    for (int mi = 0; mi < 4; mi++) {
        #pragma unroll
        for (int ni = 0; ni < 4; ni++) {
            int col = n0 + wn + ni * 8 + cq;
            float b0 = __ldg(&bias[col]), b1 = __ldg(&bias[col + 1]);
            int hh = col >> 6, d = col & 63;
            #pragma unroll
            for (int half = 0; half < 2; half++) {
                int row = m0 + wm + mi * 16 + r0 + half * 8;
                float v0 = (c[mi][ni][half * 2 + 0] + b0) * scale;
                float v1 = (c[mi][ni][half * 2 + 1] + b1) * scale;
                int bb = row >> 11, n = row & (NSEQ - 1);
                size_t idx = (((size_t)(bb * NH + hh)) * NSEQ + n) * HD + d;
                unsigned pv = pack_h2(v0, v1);
                if (z == 0)      *(unsigned*)&gQ[idx] = pv;
                else if (z == 1) *(unsigned*)&gK[idx] = pv;
                else             *(unsigned*)&gV[idx] = pv;
            }
        }
    }
}

// ---------------- output projection GEMM (1-term fp16, BK=64) --------------
__global__ __launch_bounds__(256, 2) void gemm_out(
    const float* __restrict__ bo, float* __restrict__ out)
{
    extern __shared__ __half gsm[];
    __half* sA = gsm;
    __half* sB = gsm + 2 * GTILE;

    const __half* Wp = gW + 3 * WELEM;

    const int tid = threadIdx.x, lane = tid & 31, warp = tid >> 5;
    const int m0 = blockIdx.y * 128, n0 = blockIdx.x * 128;
    const int wm = (warp & 1) * 64, wn = (warp >> 1) * 32;

    const __half* gA = gO + (size_t)m0 * DM;
    const __half* gB = Wp + (size_t)n0 * DM;

    float c[4][4][4];
    #pragma unroll
    for (int i = 0; i < 4; i++)
        #pragma unroll
        for (int j = 0; j < 4; j++)
            #pragma unroll
            for (int r = 0; r < 4; r++) c[i][j][r] = 0.0f;

    GEMM_LOAD_STAGE64(sA, sB, 0)
    CP_COMMIT();

    const int ar = lane & 15, achk = lane >> 4;
    const int br = lane & 7,  bchk = (lane >> 3) & 1;

    for (int kt = 0; kt < 16; kt++) {
        const int st = kt & 1;
        CP_WAIT0();
        __syncthreads();
        if (kt < 15) {
            GEMM_LOAD_STAGE64(sA + (st ^ 1) * GTILE, sB + (st ^ 1) * GTILE,
                              (kt + 1) * 64)
            CP_COMMIT();
        }
        GEMM_KSTEP64(0)
        GEMM_KSTEP64(1)
        GEMM_KSTEP64(2)
        GEMM_KSTEP64(3)
    }

    const int r0 = lane >> 2, cq = (lane & 3) * 2;
    #pragma unroll
    for (int mi = 0; mi < 4; mi++) {
        #pragma unroll
        for (int ni = 0; ni < 4; ni++) {
            int col = n0 + wn + ni * 8 + cq;
            float b0 = __ldg(&bo[col]), b1 = __ldg(&bo[col + 1]);
            #pragma unroll
            for (int half = 0; half < 2; half++) {
                int row = m0 + wm + mi * 16 + r0 + half * 8;
                float2 v = make_float2(c[mi][ni][half * 2 + 0] + b0,
                                       c[mi][ni][half * 2 + 1] + b1);
                *(float2*)&out[(size_t)row * DM + col] = v;
            }
        }
    }
}

// ---------------- flash attention -------------------------------------------
// S: Q fp16 x K fp16 (1 MMA). PV: P fp16 x V fp16 (1 MMA). ex2-domain softmax.
// Q fragments register-resident (loaded once). 128-key KV stages.
// smem: Q 128x64 + 2 stages x (K,V 128x64) = 81,920 B -> 2 CTAs/SM.
#define QTSZ    (128*64)             // elems per Q tile
#define KVTSZ2  (128*64)             // elems per K or V tile (128 keys)
#define KVSTG2  (2*KVTSZ2)           // elems per KV stage [K, V]
#define FLASH_SMEM ((QTSZ + 2*KVSTG2) * 2)   // bytes = 81920

__global__ __launch_bounds__(256, 2) void flash()
{
    extern __shared__ __half sm[];
    __half* sQ  = sm;                 // [128x64] swizzled
    __half* sKV = sm + QTSZ;          // [stage][K(128x64),V(128x64)]

    const int tid = threadIdx.x, lane = tid & 31, warp = tid >> 5;
    const int bh = blockIdx.y, q0 = blockIdx.x * 128;
    const size_t base = (size_t)bh * NSEQ * HD;

    // Q tile: 1024 chunks; 4 per thread
    #pragma unroll
    for (int u = 0; u < 4; u++) {
        int id = tid + u * 256;
        int r = id >> 3, c8 = id & 7;
        cp16(&sQ[swz64(r, c8)], gQ + base + (size_t)(q0 + r) * HD + c8 * 8);
    }
    // KV stage 0: K+V 128 keys = 2048 chunks; 8 per thread
    #pragma unroll
    for (int u = 0; u < 8; u++) {
        int id = tid + u * 256;
        int t = id >> 10, rem = id & 1023;
        int r = rem >> 3, c8 = rem & 7;
        size_t g = base + (size_t)r * HD + c8 * 8;
        const void* src = (t == 0) ? (const void*)(gK + g)
                                   : (const void*)(gV + g);
        cp16(&sKV[t * KVTSZ2 + swz64(r, c8)], src);
    }
    CP_COMMIT();

    float o[8][4];
    #pragma unroll
    for (int i = 0; i < 8; i++)
        #pragma unroll
        for (int j = 0; j < 4; j++) o[i][j] = 0.0f;
    float mr0 = -1e30f, mr1 = -1e30f, lr0 = 0.0f, lr1 = 0.0f;

    const int ar = lane & 15;
    const int achk = lane >> 4;          // A-operand chunk half
    const int br = lane & 7;
    const int bchk = (lane >> 3) & 1;    // B-operand chunk half

    unsigned aq[4][4];                   // Q frags, loaded once at kt==0

    for (int kt = 0; kt < NSEQ / 128; kt++) {
        const int st = kt & 1;
        CP_WAIT0();
        __syncthreads();
        if (kt == 0) {
            // hoist Q fragments into registers (invariant across tiles)
            #pragma unroll
            for (int kk = 0; kk < 4; kk++) {
                int aoff = swz64(warp * 16 + ar, kk * 2 + achk);
                ldm_x4(aq[kk][0], aq[kk][1], aq[kk][2], aq[kk][3], &sQ[aoff]);
            }
        }
        if (kt < NSEQ / 128 - 1) {
            __half* d = sKV + (st ^ 1) * KVSTG2;
            size_t kb = base + (size_t)(kt + 1) * 128 * HD;
            #pragma unroll
            for (int u = 0; u < 8; u++) {
                int id = tid + u * 256;
                int t = id >> 10, rem = id & 1023;
                int r = rem >> 3, c8 = rem & 7;
                size_t g = kb + (size_t)r * HD + c8 * 8;
                const void* src = (t == 0) ? (const void*)(gK + g)
                                           : (const void*)(gV + g);
                cp16(&d[t * KVTSZ2 + swz64(r, c8)], src);
            }
            CP_COMMIT();
        }

        #pragma unroll
        for (int sub = 0; sub < 2; sub++) {
            const __half* Ks = sKV + st * KVSTG2 + sub * (64 * 64);
            const __half* Vs = sKV + st * KVSTG2 + KVTSZ2 + sub * (64 * 64);

            float s[8][4];
            #pragma unroll
            for (int i = 0; i < 8; i++)
                #pragma unroll
                for (int j = 0; j < 4; j++) s[i][j] = 0.0f;

            // S = Q.K^T — 1 term, Q frags from registers
            #pragma unroll
            for (int kk = 0; kk < 4; kk++) {
                #pragma unroll
                for (int nh = 0; nh < 2; nh++) {
                    unsigned kb4[4][2];
                    #pragma unroll
                    for (int nq = 0; nq < 4; nq++) {
                        int krow = (nh * 4 + nq) * 8 + br;
                        int koff = swz64(krow, kk * 2 + bchk);
                        ldm_x2(kb4[nq][0], kb4[nq][1], &Ks[koff]);
                    }
                    #pragma unroll
                    for (int nq = 0; nq < 4; nq++)
                        mma16816h(s[nh * 4 + nq], aq[kk][0], aq[kk][1],
                                  aq[kk][2], aq[kk][3],
                                  kb4[nq][0], kb4[nq][1]);
                }
            }

            float mx0 = -1e30f, mx1 = -1e30f;
            #pragma unroll
            for (int ni = 0; ni < 8; ni++) {
                mx0 = fmaxf(mx0, fmaxf(s[ni][0], s[ni][1]));
                mx1 = fmaxf(mx1, fmaxf(s[ni][2], s[ni][3]));
            }
            mx0 = fmaxf(mx0, __shfl_xor_sync(0xffffffffu, mx0, 1));
            mx0 = fmaxf(mx0, __shfl_xor_sync(0xffffffffu, mx0, 2));
            mx1 = fmaxf(mx1, __shfl_xor_sync(0xffffffffu, mx1, 1));
            mx1 = fmaxf(mx1, __shfl_xor_sync(0xffffffffu, mx1, 2));

            float nm0 = fmaxf(mr0, mx0), nm1 = fmaxf(mr1, mx1);
            float cr0 = ex2a(mr0 - nm0), cr1 = ex2a(mr1 - nm1);
            mr0 = nm0; mr1 = nm1;

            float sum0 = 0.0f, sum1 = 0.0f;
            #pragma unroll
            for (int ni = 0; ni < 8; ni++) {
                s[ni][0] = ex2a(s[ni][0] - nm0);
                s[ni][1] = ex2a(s[ni][1] - nm0);
                s[ni][2] = ex2a(s[ni][2] - nm1);
                s[ni][3] = ex2a(s[ni][3] - nm1);
                sum0 += s[ni][0] + s[ni][1];
                sum1 += s[ni][2] + s[ni][3];
            }
            sum0 += __shfl_xor_sync(0xffffffffu, sum0, 1);
            sum0 += __shfl_xor_sync(0xffffffffu, sum0, 2);
            sum1 += __shfl_xor_sync(0xffffffffu, sum1, 1);
            sum1 += __shfl_xor_sync(0xffffffffu, sum1, 2);
            lr0 = lr0 * cr0 + sum0;
            lr1 = lr1 * cr1 + sum1;
            #pragma unroll
            for (int dj = 0; dj < 8; dj++) {
                o[dj][0] *= cr0; o[dj][1] *= cr0;
                o[dj][2] *= cr1; o[dj][3] *= cr1;
            }

            // O += P(fp16) . V(fp16) — term-major over dj-quads
            #pragma unroll
            for (int kk = 0; kk < 4; kk++) {
                unsigned p0 = pack_h2(s[2*kk][0],   s[2*kk][1]);
                unsigned p1 = pack_h2(s[2*kk][2],   s[2*kk][3]);
                unsigned p2 = pack_h2(s[2*kk+1][0], s[2*kk+1][1]);
                unsigned p3 = pack_h2(s[2*kk+1][2], s[2*kk+1][3]);
                int vrow = kk * 16 + ar;
                #pragma unroll
                for (int dh = 0; dh < 2; dh++) {
                    unsigned vb4[4][2];
                    #pragma unroll
                    for (int dq = 0; dq < 4; dq++) {
                        int voff = swz64(vrow, dh * 4 + dq);
                        ldm_x2t(vb4[dq][0], vb4[dq][1], &Vs[voff]);
                    }
                    #pragma unroll
                    for (int dq = 0; dq < 4; dq++)
                        mma16816h(o[dh * 4 + dq], p0, p1, p2, p3,
                                  vb4[dq][0], vb4[dq][1]);
                }
            }
        }
    }

    const int b = bh >> 4, h = bh & 15;
    const int row0 = q0 + warp * 16 + (lane >> 2);
    const float inv0 = 1.0f / lr0, inv1 = 1.0f / lr1;
    const size_t rb = ((size_t)(b * NSEQ) + row0) * DM + h * HD;
    #pragma unroll
    for (int dj = 0; dj < 8; dj++) {
        int d = dj * 8 + (lane & 3) * 2;
        *(unsigned*)&gO[rb + d] = pack_h2(o[dj][0] * inv0, o[dj][1] * inv0);
        *(unsigned*)&gO[rb + (size_t)8 * DM + d] =
            pack_h2(o[dj][2] * inv1, o[dj][3] * inv1);
    }
}

// ---------------------------------------------------------------------------
extern "C" void kernel_launch(void* const* d_in, const int* in_sizes, int n_in,
                              void* d_out, int out_size)
{
    (void)in_sizes; (void)n_in; (void)out_size;
    const float* queries = (const float*)d_in[0];
    const float* keys    = (const float*)d_in[1];
    const float* values  = (const float*)d_in[2];
    const float* Wq = (const float*)d_in[3];
    const float* bq = (const float*)d_in[4];
    const float* Wk = (const float*)d_in[5];
    const float* bk = (const float*)d_in[6];
    const float* Wv = (const float*)d_in[7];
    const float* bv = (const float*)d_in[8];
    const float* Wo = (const float*)d_in[9];
    const float* bo = (const float*)d_in[10];
    float* out = (float*)d_out;

    cudaFuncSetAttribute(flash, cudaFuncAttributeMaxDynamicSharedMemorySize,
                         FLASH_SMEM);
    cudaFuncSetAttribute(gemm_qkv, cudaFuncAttributeMaxDynamicSharedMemorySize,
                         GSMEM);
    cudaFuncSetAttribute(gemm_out, cudaFuncAttributeMaxDynamicSharedMemorySize,
                         GSMEM);

    // fp32 -> fp16 (single launch; L2-resident output for gemm_qkv)
    split_all<<<4096, 256>>>(queries, keys, values, Wq, Wk, Wv, Wo);

    // QKV projections
    gemm_qkv<<<dim3(DM / 128, MROWS / 128, 3), 256, GSMEM>>>(bq, bk, bv);

    // attention
    flash<<<dim3(NSEQ / 128, NB * NH), 256, FLASH_SMEM>>>();

    // output projection
    gemm_out<<<dim3(DM / 128, MROWS / 128), 256, GSMEM>>>(bo, out);
}